// round 12
// baseline (speedup 1.0000x reference)
#include <cuda_runtime.h>
#include <cuda_bf16.h>
#include <cstdint>

#define NP    64
#define NANG  2016     // 64*63/2
#define SEG   504      // NANG / 4
#define XSP   132      // f32 pitch for staged X rows (bank-free B-frag loads)

// Pre-packed m16n8k16 A-fragments of (mus-scaled) R, hi/lo bf16 split.
// Slot = (i_tile*4 + s_ktile)*32 + lane ; .x=a0 .y=a1 .z=a2 .w=a3
__device__ uint4 g_fragH[512];
__device__ uint4 g_fragL[512];

// ---------------------------------------------------------------------------
// helpers
// ---------------------------------------------------------------------------
__device__ __forceinline__ uint32_t pack_bf16x2(float lo, float hi) {
    uint32_t r;
    asm("cvt.rn.bf16x2.f32 %0, %1, %2;" : "=r"(r) : "f"(hi), "f"(lo));
    return r;
}
__device__ __forceinline__ float bf16_hi_val(float v) {
    return __bfloat162float(__float2bfloat16(v));
}
__device__ __forceinline__ void mma_bf16(float& d0, float& d1, float& d2, float& d3,
                                         uint32_t a0, uint32_t a1, uint32_t a2, uint32_t a3,
                                         uint32_t b0, uint32_t b1) {
    asm("mma.sync.aligned.m16n8k16.row.col.f32.bf16.bf16.f32 "
        "{%0,%1,%2,%3}, {%4,%5,%6,%7}, {%8,%9}, {%0,%1,%2,%3};"
        : "+f"(d0), "+f"(d1), "+f"(d2), "+f"(d3)
        : "r"(a0), "r"(a1), "r"(a2), "r"(a3), "r"(b0), "r"(b1));
}
__device__ __forceinline__ uint32_t smem_u32ptr(const void* p) {
    return (uint32_t)__cvta_generic_to_shared(p);
}
__device__ __forceinline__ void cp_async16(uint32_t dst, const void* src, int nbytes) {
    asm volatile("cp.async.ca.shared.global [%0], [%1], 16, %2;"
                 :: "r"(dst), "l"(src), "r"(nbytes));
}

// ---------------------------------------------------------------------------
// Kernel 1: build R = P3*P2*P1*P0 (4 parallel 504-rotation segments, 3 fp32
// matmuls to combine), then emit mus-scaled hi/lo bf16 A-fragments.
// (unchanged from R11 — verified rel_err 4.4e-6)
// ---------------------------------------------------------------------------
#define BR_SMEM (16384 * 5)

__global__ void build_R_kernel(const float* __restrict__ angles,
                               const float* __restrict__ mus) {
    extern __shared__ __align__(16) char smem[];
    float2* cs = reinterpret_cast<float2*>(smem);
    float*  Pm[4];
#pragma unroll
    for (int s = 0; s < 4; ++s) Pm[s] = reinterpret_cast<float*>(smem + 16384 + s * 16384);

    const int tid  = threadIdx.x;
    const int g4   = tid >> 6;
    const int lane = tid & 63;

    for (int a = tid; a < NANG; a += 256) {
        float s, c;
        sincosf(angles[a], &s, &c);
        cs[a] = make_float2(c, s);
    }
    {
        float* Y = Pm[g4];
#pragma unroll
        for (int i = 0; i < NP; ++i) Y[i * NP + lane] = (i == lane) ? 1.0f : 0.0f;
    }
    __syncthreads();

    {
        float* Y = Pm[g4];
        const int segStart = g4 * SEG, segEnd = segStart + SEG;
        int F = 0;
        for (int t = 0; t < NP - 1; ++t) {
            const int fanLen = NP - 1 - t;
            int lo = F > segStart ? F : segStart;
            int hi = (F + fanLen) < segEnd ? (F + fanLen) : segEnd;
            if (lo < hi) {
                float vt = Y[t * NP + lane];
                int idx = lo;
                int ib = t + 1 + (lo - F);
                int cnt = hi - lo;
                const int rem = cnt & 7;
                for (int u = 0; u < rem; ++u) {
                    float2 a = cs[idx + u];
                    float vb = Y[(ib + u) * NP + lane];
                    float nb = fmaf(a.y, vt, a.x * vb);
                    vt = fmaf(a.x, vt, -a.y * vb);
                    Y[(ib + u) * NP + lane] = nb;
                }
                idx += rem; ib += rem;
                for (; idx < hi; ib += 8, idx += 8) {
                    float2 a0 = cs[idx+0], a1 = cs[idx+1], a2 = cs[idx+2], a3 = cs[idx+3];
                    float2 a4 = cs[idx+4], a5 = cs[idx+5], a6 = cs[idx+6], a7 = cs[idx+7];
                    float vb0 = Y[(ib+0)*NP+lane], vb1 = Y[(ib+1)*NP+lane];
                    float vb2 = Y[(ib+2)*NP+lane], vb3 = Y[(ib+3)*NP+lane];
                    float vb4 = Y[(ib+4)*NP+lane], vb5 = Y[(ib+5)*NP+lane];
                    float vb6 = Y[(ib+6)*NP+lane], vb7 = Y[(ib+7)*NP+lane];
                    float nb0 = fmaf(a0.y, vt, a0.x*vb0); vt = fmaf(a0.x, vt, -a0.y*vb0);
                    float nb1 = fmaf(a1.y, vt, a1.x*vb1); vt = fmaf(a1.x, vt, -a1.y*vb1);
                    float nb2 = fmaf(a2.y, vt, a2.x*vb2); vt = fmaf(a2.x, vt, -a2.y*vb2);
                    float nb3 = fmaf(a3.y, vt, a3.x*vb3); vt = fmaf(a3.x, vt, -a3.y*vb3);
                    float nb4 = fmaf(a4.y, vt, a4.x*vb4); vt = fmaf(a4.x, vt, -a4.y*vb4);
                    float nb5 = fmaf(a5.y, vt, a5.x*vb5); vt = fmaf(a5.x, vt, -a5.y*vb5);
                    float nb6 = fmaf(a6.y, vt, a6.x*vb6); vt = fmaf(a6.x, vt, -a6.y*vb6);
                    float nb7 = fmaf(a7.y, vt, a7.x*vb7); vt = fmaf(a7.x, vt, -a7.y*vb7);
                    Y[(ib+0)*NP+lane] = nb0; Y[(ib+1)*NP+lane] = nb1;
                    Y[(ib+2)*NP+lane] = nb2; Y[(ib+3)*NP+lane] = nb3;
                    Y[(ib+4)*NP+lane] = nb4; Y[(ib+5)*NP+lane] = nb5;
                    Y[(ib+6)*NP+lane] = nb6; Y[(ib+7)*NP+lane] = nb7;
                }
                Y[t * NP + lane] = vt;
            }
            F += fanLen;
            if (F >= segEnd) break;
        }
    }
    __syncthreads();

    float* T0   = reinterpret_cast<float*>(smem);
    float* T1   = Pm[0];
    float* Rfin = T0;
    const int mi = tid >> 2;
    const int jq = (tid & 3) * 16;

#define MATMUL(Cm, Am, Bm)                                                       \
    {                                                                            \
        float accm[16];                                                          \
        _Pragma("unroll")                                                        \
        for (int u = 0; u < 16; ++u) accm[u] = 0.0f;                             \
        for (int k = 0; k < NP; ++k) {                                           \
            float av = (Am)[mi * NP + k];                                        \
            const float4* br = reinterpret_cast<const float4*>(&(Bm)[k * NP + jq]); \
            float4 b0 = br[0], b1 = br[1], b2 = br[2], b3 = br[3];               \
            accm[0]  = fmaf(av, b0.x, accm[0]);  accm[1]  = fmaf(av, b0.y, accm[1]);  \
            accm[2]  = fmaf(av, b0.z, accm[2]);  accm[3]  = fmaf(av, b0.w, accm[3]);  \
            accm[4]  = fmaf(av, b1.x, accm[4]);  accm[5]  = fmaf(av, b1.y, accm[5]);  \
            accm[6]  = fmaf(av, b1.z, accm[6]);  accm[7]  = fmaf(av, b1.w, accm[7]);  \
            accm[8]  = fmaf(av, b2.x, accm[8]);  accm[9]  = fmaf(av, b2.y, accm[9]);  \
            accm[10] = fmaf(av, b2.z, accm[10]); accm[11] = fmaf(av, b2.w, accm[11]); \
            accm[12] = fmaf(av, b3.x, accm[12]); accm[13] = fmaf(av, b3.y, accm[13]); \
            accm[14] = fmaf(av, b3.z, accm[14]); accm[15] = fmaf(av, b3.w, accm[15]); \
        }                                                                        \
        __syncthreads();                                                         \
        _Pragma("unroll")                                                        \
        for (int u = 0; u < 16; ++u) (Cm)[mi * NP + jq + u] = accm[u];           \
        __syncthreads();                                                         \
    }

    MATMUL(T0, Pm[1], Pm[0]);
    MATMUL(T1, Pm[2], T0);
    MATMUL(Rfin, Pm[3], T1);
#undef MATMUL

#pragma unroll
    for (int pass = 0; pass < 2; ++pass) {
        const int slot = tid + pass * 256;
        const int is = slot >> 5, ln = slot & 31;
        const int it = is >> 2, s = is & 3;
        const int g = ln >> 2, t = ln & 3;
        const int r0 = 16 * it + g, r1 = r0 + 8;
        const int c0 = 16 * s + 2 * t, c1 = c0 + 8;
        const float m0 = mus[r0], m1 = mus[r1];
        float v00 = Rfin[r0 * NP + c0] * m0,     v01 = Rfin[r0 * NP + c0 + 1] * m0;
        float v10 = Rfin[r1 * NP + c0] * m1,     v11 = Rfin[r1 * NP + c0 + 1] * m1;
        float v02 = Rfin[r0 * NP + c1] * m0,     v03 = Rfin[r0 * NP + c1 + 1] * m0;
        float v12 = Rfin[r1 * NP + c1] * m1,     v13 = Rfin[r1 * NP + c1 + 1] * m1;
        uint4 hi, lo;
        hi.x = pack_bf16x2(v00, v01); hi.y = pack_bf16x2(v10, v11);
        hi.z = pack_bf16x2(v02, v03); hi.w = pack_bf16x2(v12, v13);
        lo.x = pack_bf16x2(v00 - bf16_hi_val(v00), v01 - bf16_hi_val(v01));
        lo.y = pack_bf16x2(v10 - bf16_hi_val(v10), v11 - bf16_hi_val(v11));
        lo.z = pack_bf16x2(v02 - bf16_hi_val(v02), v03 - bf16_hi_val(v03));
        lo.w = pack_bf16x2(v12 - bf16_hi_val(v12), v13 - bf16_hi_val(v13));
        g_fragH[slot] = hi;
        g_fragL[slot] = lo;
    }
}

// ---------------------------------------------------------------------------
// Kernel 2: out[64, N] = R @ X, warp HMMA, hi/lo split, 3 fused passes.
// v2: cp.async stages raw f32 X [k][c] (pitch 132, bank-free B loads) — no
// per-thread staging buffers, no Xlo array. A-frags loaded ONCE per (s,i)
// and reused by all 3 passes. 3 CTAs/SM target.
// smem (u32): FRAGH 0, FRAGL 2048, XS 4096..12544  -> 50176 B.
// ---------------------------------------------------------------------------
#define SM_FRAGH 0
#define SM_FRAGL 2048
#define SM_XS    4096
#define APPLY_SMEM (12544 * 4)

__global__ __launch_bounds__(256, 3)
void apply_mma_kernel(const float* __restrict__ X,
                      float* __restrict__ out,
                      int N) {
    extern __shared__ __align__(16) uint32_t sm[];
    uint4* fragH = reinterpret_cast<uint4*>(sm + SM_FRAGH);
    uint4* fragL = reinterpret_cast<uint4*>(sm + SM_FRAGL);
    float* Xs    = reinterpret_cast<float*>(sm + SM_XS);

    const int tid  = threadIdx.x;
    const int wid  = tid >> 5;
    const int lane = tid & 31;
    const int g    = lane >> 2;
    const int t    = lane & 3;
    const int col0 = blockIdx.x * 128;
    const uint32_t sbase = smem_u32ptr(sm);

    // --- Stage A-fragments via cp.async (1024 x 16B) ---
#pragma unroll
    for (int j = 0; j < 4; ++j) {
        const int slot = tid + 256 * j;
        if (slot < 512) {
            cp_async16(sbase + (SM_FRAGH + slot * 4) * 4, &g_fragH[slot], 16);
        } else {
            cp_async16(sbase + (SM_FRAGL + (slot - 512) * 4) * 4, &g_fragL[slot - 512], 16);
        }
    }

    // --- Stage X tile raw f32 via cp.async: 64 rows x 32 chunks of 16B ---
#pragma unroll
    for (int j = 0; j < 8; ++j) {
        const int q   = tid + 256 * j;
        const int row = q >> 5;
        const int cc  = (q & 31) * 4;
        const int cg  = col0 + cc;
        int rem = N - cg;                       // columns remaining
        int nb  = rem >= 4 ? 16 : (rem > 0 ? rem * 4 : 0);
        cp_async16(sbase + (SM_XS + row * XSP + cc) * 4,
                   X + (size_t)row * N + cg, nb);
    }
    asm volatile("cp.async.commit_group;" ::: "memory");
    asm volatile("cp.async.wait_group 0;" ::: "memory");
    __syncthreads();

    float acc[4][2][4];
#pragma unroll
    for (int i = 0; i < 4; ++i)
#pragma unroll
        for (int jj = 0; jj < 2; ++jj)
#pragma unroll
            for (int r = 0; r < 4; ++r) acc[i][jj][r] = 0.0f;

    const int cA = wid * 16 + g;    // jj=0 column; jj=1 is cA+8

#pragma unroll
    for (int s = 0; s < 4; ++s) {
        const int k0 = 16 * s + 2 * t;
        // 8 conflict-free LDS.32: k, k+1, k+8, k+9 for two columns
        float fa0 = Xs[(k0 + 0) * XSP + cA];
        float fa1 = Xs[(k0 + 1) * XSP + cA];
        float fa8 = Xs[(k0 + 8) * XSP + cA];
        float fa9 = Xs[(k0 + 9) * XSP + cA];
        float fb0 = Xs[(k0 + 0) * XSP + cA + 8];
        float fb1 = Xs[(k0 + 1) * XSP + cA + 8];
        float fb8 = Xs[(k0 + 8) * XSP + cA + 8];
        float fb9 = Xs[(k0 + 9) * XSP + cA + 8];

        uint32_t bHi00 = pack_bf16x2(fa0, fa1);
        uint32_t bHi01 = pack_bf16x2(fa8, fa9);
        uint32_t bHi10 = pack_bf16x2(fb0, fb1);
        uint32_t bHi11 = pack_bf16x2(fb8, fb9);
        uint32_t bLo00 = pack_bf16x2(fa0 - bf16_hi_val(fa0), fa1 - bf16_hi_val(fa1));
        uint32_t bLo01 = pack_bf16x2(fa8 - bf16_hi_val(fa8), fa9 - bf16_hi_val(fa9));
        uint32_t bLo10 = pack_bf16x2(fb0 - bf16_hi_val(fb0), fb1 - bf16_hi_val(fb1));
        uint32_t bLo11 = pack_bf16x2(fb8 - bf16_hi_val(fb8), fb9 - bf16_hi_val(fb9));

#pragma unroll
        for (int i = 0; i < 4; ++i) {
            uint4 fH = fragH[(i * 4 + s) * 32 + lane];
            uint4 fL = fragL[(i * 4 + s) * 32 + lane];
            mma_bf16(acc[i][0][0], acc[i][0][1], acc[i][0][2], acc[i][0][3],
                     fH.x, fH.y, fH.z, fH.w, bHi00, bHi01);
            mma_bf16(acc[i][1][0], acc[i][1][1], acc[i][1][2], acc[i][1][3],
                     fH.x, fH.y, fH.z, fH.w, bHi10, bHi11);
            mma_bf16(acc[i][0][0], acc[i][0][1], acc[i][0][2], acc[i][0][3],
                     fH.x, fH.y, fH.z, fH.w, bLo00, bLo01);
            mma_bf16(acc[i][1][0], acc[i][1][1], acc[i][1][2], acc[i][1][3],
                     fH.x, fH.y, fH.z, fH.w, bLo10, bLo11);
            mma_bf16(acc[i][0][0], acc[i][0][1], acc[i][0][2], acc[i][0][3],
                     fL.x, fL.y, fL.z, fL.w, bHi00, bHi01);
            mma_bf16(acc[i][1][0], acc[i][1][1], acc[i][1][2], acc[i][1][3],
                     fL.x, fL.y, fL.z, fL.w, bHi10, bHi11);
        }
    }

    // --- Epilogue: adjacent-column float2 stores ---
#pragma unroll
    for (int i = 0; i < 4; ++i) {
#pragma unroll
        for (int jj = 0; jj < 2; ++jj) {
            const int colb = col0 + wid * 16 + jj * 8 + 2 * t;
            if (colb < N) {
                const int row = 16 * i + g;
                *reinterpret_cast<float2*>(out + (size_t)row * N + colb) =
                    make_float2(acc[i][jj][0], acc[i][jj][1]);
                *reinterpret_cast<float2*>(out + (size_t)(row + 8) * N + colb) =
                    make_float2(acc[i][jj][2], acc[i][jj][3]);
            }
        }
    }
}

// ---------------------------------------------------------------------------
// Inputs (metadata order): X [64*500000] f32, angles [2016] f32, mus [64] f32.
// Output: [64*500000] f32.
// ---------------------------------------------------------------------------
extern "C" void kernel_launch(void* const* d_in, const int* in_sizes, int n_in,
                              void* d_out, int out_size) {
    const float* X      = (const float*)d_in[0];
    const float* angles = (const float*)d_in[1];
    const float* mus    = (const float*)d_in[2];
    float* out = (float*)d_out;

    const int N = in_sizes[0] / NP;  // 500000

    cudaFuncSetAttribute(build_R_kernel,
                         cudaFuncAttributeMaxDynamicSharedMemorySize, BR_SMEM);
    build_R_kernel<<<1, 256, BR_SMEM>>>(angles, mus);

    cudaFuncSetAttribute(apply_mma_kernel,
                         cudaFuncAttributeMaxDynamicSharedMemorySize, APPLY_SMEM);
    const int grid = (N + 127) / 128;  // 3907
    apply_mma_kernel<<<grid, 256, APPLY_SMEM>>>(X, out, N);
}

// round 13
// speedup vs baseline: 1.4539x; 1.4539x over previous
#include <cuda_runtime.h>
#include <cuda_bf16.h>
#include <cstdint>

#define NP    64
#define NANG  2016     // 64*63/2
#define SEG   504      // NANG / 4
#define PITCH 36       // u32 per staged 64-bf16 row: conflict-free + 16B-aligned

// Pre-packed m16n8k16 A-fragments of (mus-scaled) R, hi/lo bf16 split.
// Slot = (i_tile*4 + s_ktile)*32 + lane ; .x=a0 .y=a1 .z=a2 .w=a3
__device__ uint4 g_fragH[512];
__device__ uint4 g_fragL[512];

// ---------------------------------------------------------------------------
// helpers
// ---------------------------------------------------------------------------
__device__ __forceinline__ uint32_t pack_bf16x2(float lo, float hi) {
    uint32_t r;
    asm("cvt.rn.bf16x2.f32 %0, %1, %2;" : "=r"(r) : "f"(hi), "f"(lo));
    return r;
}
__device__ __forceinline__ float bf16_hi_val(float v) {
    return __bfloat162float(__float2bfloat16(v));
}
__device__ __forceinline__ void mma_bf16(float& d0, float& d1, float& d2, float& d3,
                                         uint32_t a0, uint32_t a1, uint32_t a2, uint32_t a3,
                                         uint32_t b0, uint32_t b1) {
    asm("mma.sync.aligned.m16n8k16.row.col.f32.bf16.bf16.f32 "
        "{%0,%1,%2,%3}, {%4,%5,%6,%7}, {%8,%9}, {%0,%1,%2,%3};"
        : "+f"(d0), "+f"(d1), "+f"(d2), "+f"(d3)
        : "r"(a0), "r"(a1), "r"(a2), "r"(a3), "r"(b0), "r"(b1));
}

// ---------------------------------------------------------------------------
// Kernel 1: build R = P3*P2*P1*P0 (4 parallel 504-rotation segments, 3 fp32
// matmuls to combine), then emit mus-scaled hi/lo bf16 A-fragments.
// (unchanged from R11 — verified rel_err 4.4e-6)
// ---------------------------------------------------------------------------
#define BR_SMEM (16384 * 5)

__global__ void build_R_kernel(const float* __restrict__ angles,
                               const float* __restrict__ mus) {
    extern __shared__ __align__(16) char smem[];
    float2* cs = reinterpret_cast<float2*>(smem);
    float*  Pm[4];
#pragma unroll
    for (int s = 0; s < 4; ++s) Pm[s] = reinterpret_cast<float*>(smem + 16384 + s * 16384);

    const int tid  = threadIdx.x;
    const int g4   = tid >> 6;
    const int lane = tid & 63;

    for (int a = tid; a < NANG; a += 256) {
        float s, c;
        sincosf(angles[a], &s, &c);
        cs[a] = make_float2(c, s);
    }
    {
        float* Y = Pm[g4];
#pragma unroll
        for (int i = 0; i < NP; ++i) Y[i * NP + lane] = (i == lane) ? 1.0f : 0.0f;
    }
    __syncthreads();

    {
        float* Y = Pm[g4];
        const int segStart = g4 * SEG, segEnd = segStart + SEG;
        int F = 0;
        for (int t = 0; t < NP - 1; ++t) {
            const int fanLen = NP - 1 - t;
            int lo = F > segStart ? F : segStart;
            int hi = (F + fanLen) < segEnd ? (F + fanLen) : segEnd;
            if (lo < hi) {
                float vt = Y[t * NP + lane];
                int idx = lo;
                int ib = t + 1 + (lo - F);
                int cnt = hi - lo;
                const int rem = cnt & 7;
                for (int u = 0; u < rem; ++u) {
                    float2 a = cs[idx + u];
                    float vb = Y[(ib + u) * NP + lane];
                    float nb = fmaf(a.y, vt, a.x * vb);
                    vt = fmaf(a.x, vt, -a.y * vb);
                    Y[(ib + u) * NP + lane] = nb;
                }
                idx += rem; ib += rem;
                for (; idx < hi; ib += 8, idx += 8) {
                    float2 a0 = cs[idx+0], a1 = cs[idx+1], a2 = cs[idx+2], a3 = cs[idx+3];
                    float2 a4 = cs[idx+4], a5 = cs[idx+5], a6 = cs[idx+6], a7 = cs[idx+7];
                    float vb0 = Y[(ib+0)*NP+lane], vb1 = Y[(ib+1)*NP+lane];
                    float vb2 = Y[(ib+2)*NP+lane], vb3 = Y[(ib+3)*NP+lane];
                    float vb4 = Y[(ib+4)*NP+lane], vb5 = Y[(ib+5)*NP+lane];
                    float vb6 = Y[(ib+6)*NP+lane], vb7 = Y[(ib+7)*NP+lane];
                    float nb0 = fmaf(a0.y, vt, a0.x*vb0); vt = fmaf(a0.x, vt, -a0.y*vb0);
                    float nb1 = fmaf(a1.y, vt, a1.x*vb1); vt = fmaf(a1.x, vt, -a1.y*vb1);
                    float nb2 = fmaf(a2.y, vt, a2.x*vb2); vt = fmaf(a2.x, vt, -a2.y*vb2);
                    float nb3 = fmaf(a3.y, vt, a3.x*vb3); vt = fmaf(a3.x, vt, -a3.y*vb3);
                    float nb4 = fmaf(a4.y, vt, a4.x*vb4); vt = fmaf(a4.x, vt, -a4.y*vb4);
                    float nb5 = fmaf(a5.y, vt, a5.x*vb5); vt = fmaf(a5.x, vt, -a5.y*vb5);
                    float nb6 = fmaf(a6.y, vt, a6.x*vb6); vt = fmaf(a6.x, vt, -a6.y*vb6);
                    float nb7 = fmaf(a7.y, vt, a7.x*vb7); vt = fmaf(a7.x, vt, -a7.y*vb7);
                    Y[(ib+0)*NP+lane] = nb0; Y[(ib+1)*NP+lane] = nb1;
                    Y[(ib+2)*NP+lane] = nb2; Y[(ib+3)*NP+lane] = nb3;
                    Y[(ib+4)*NP+lane] = nb4; Y[(ib+5)*NP+lane] = nb5;
                    Y[(ib+6)*NP+lane] = nb6; Y[(ib+7)*NP+lane] = nb7;
                }
                Y[t * NP + lane] = vt;
            }
            F += fanLen;
            if (F >= segEnd) break;
        }
    }
    __syncthreads();

    float* T0   = reinterpret_cast<float*>(smem);
    float* T1   = Pm[0];
    float* Rfin = T0;
    const int mi = tid >> 2;
    const int jq = (tid & 3) * 16;

#define MATMUL(Cm, Am, Bm)                                                       \
    {                                                                            \
        float accm[16];                                                          \
        _Pragma("unroll")                                                        \
        for (int u = 0; u < 16; ++u) accm[u] = 0.0f;                             \
        for (int k = 0; k < NP; ++k) {                                           \
            float av = (Am)[mi * NP + k];                                        \
            const float4* br = reinterpret_cast<const float4*>(&(Bm)[k * NP + jq]); \
            float4 b0 = br[0], b1 = br[1], b2 = br[2], b3 = br[3];               \
            accm[0]  = fmaf(av, b0.x, accm[0]);  accm[1]  = fmaf(av, b0.y, accm[1]);  \
            accm[2]  = fmaf(av, b0.z, accm[2]);  accm[3]  = fmaf(av, b0.w, accm[3]);  \
            accm[4]  = fmaf(av, b1.x, accm[4]);  accm[5]  = fmaf(av, b1.y, accm[5]);  \
            accm[6]  = fmaf(av, b1.z, accm[6]);  accm[7]  = fmaf(av, b1.w, accm[7]);  \
            accm[8]  = fmaf(av, b2.x, accm[8]);  accm[9]  = fmaf(av, b2.y, accm[9]);  \
            accm[10] = fmaf(av, b2.z, accm[10]); accm[11] = fmaf(av, b2.w, accm[11]); \
            accm[12] = fmaf(av, b3.x, accm[12]); accm[13] = fmaf(av, b3.y, accm[13]); \
            accm[14] = fmaf(av, b3.z, accm[14]); accm[15] = fmaf(av, b3.w, accm[15]); \
        }                                                                        \
        __syncthreads();                                                         \
        _Pragma("unroll")                                                        \
        for (int u = 0; u < 16; ++u) (Cm)[mi * NP + jq + u] = accm[u];           \
        __syncthreads();                                                         \
    }

    MATMUL(T0, Pm[1], Pm[0]);
    MATMUL(T1, Pm[2], T0);
    MATMUL(Rfin, Pm[3], T1);
#undef MATMUL

#pragma unroll
    for (int pass = 0; pass < 2; ++pass) {
        const int slot = tid + pass * 256;
        const int is = slot >> 5, ln = slot & 31;
        const int it = is >> 2, s = is & 3;
        const int g = ln >> 2, t = ln & 3;
        const int r0 = 16 * it + g, r1 = r0 + 8;
        const int c0 = 16 * s + 2 * t, c1 = c0 + 8;
        const float m0 = mus[r0], m1 = mus[r1];
        float v00 = Rfin[r0 * NP + c0] * m0,     v01 = Rfin[r0 * NP + c0 + 1] * m0;
        float v10 = Rfin[r1 * NP + c0] * m1,     v11 = Rfin[r1 * NP + c0 + 1] * m1;
        float v02 = Rfin[r0 * NP + c1] * m0,     v03 = Rfin[r0 * NP + c1 + 1] * m0;
        float v12 = Rfin[r1 * NP + c1] * m1,     v13 = Rfin[r1 * NP + c1 + 1] * m1;
        uint4 hi, lo;
        hi.x = pack_bf16x2(v00, v01); hi.y = pack_bf16x2(v10, v11);
        hi.z = pack_bf16x2(v02, v03); hi.w = pack_bf16x2(v12, v13);
        lo.x = pack_bf16x2(v00 - bf16_hi_val(v00), v01 - bf16_hi_val(v01));
        lo.y = pack_bf16x2(v10 - bf16_hi_val(v10), v11 - bf16_hi_val(v11));
        lo.z = pack_bf16x2(v02 - bf16_hi_val(v02), v03 - bf16_hi_val(v03));
        lo.w = pack_bf16x2(v12 - bf16_hi_val(v12), v13 - bf16_hi_val(v13));
        g_fragH[slot] = hi;
        g_fragL[slot] = lo;
    }
}

// ---------------------------------------------------------------------------
// Kernel 2: out[64, N] = R @ X, warp HMMA, hi/lo split, FUSED 3 passes.
// Staging = R11 style (coalesced LDG -> convert once -> STS.128, pitch 36),
// chunked 2x16 to keep regs low (3 CTAs/SM). Main loop = R12 style fusion:
// A-frags loaded once per (s,i), B-frags once per s, 6 MMAs each.
// smem (u32): FRAGH 0, FRAGL 2048, XHI 4096, XLO 8704, total 13312 (53248B).
// ---------------------------------------------------------------------------
#define SM_FRAGH 0
#define SM_FRAGL 2048
#define SM_XHI   4096
#define SM_XLO   8704
#define APPLY_SMEM (13312 * 4)

__global__ __launch_bounds__(256, 3)
void apply_mma_kernel(const float* __restrict__ X,
                      float* __restrict__ out,
                      int N) {
    extern __shared__ __align__(16) uint32_t sm[];
    uint4*    fragH = reinterpret_cast<uint4*>(sm + SM_FRAGH);
    uint4*    fragL = reinterpret_cast<uint4*>(sm + SM_FRAGL);
    uint32_t* Xhi   = sm + SM_XHI;
    uint32_t* Xlo   = sm + SM_XLO;

    const int tid  = threadIdx.x;
    const int wid  = tid >> 5;
    const int lane = tid & 31;
    const int g    = lane >> 2;
    const int t    = lane & 3;
    const int col0 = blockIdx.x * 128;

    // --- Stage pre-packed R fragments (4x LDG.128 + STS.128) ---
    fragH[tid]       = g_fragH[tid];
    fragH[tid + 256] = g_fragH[tid + 256];
    fragL[tid]       = g_fragL[tid];
    fragL[tid + 256] = g_fragL[tid + 256];

    // --- Stage X tile (hi/lo bf16), chunked 2x16 to limit live registers ---
    {
        const int c  = tid & 127;
        const int kh = (tid >> 7) * 32;
        const int cg = (col0 + c < N) ? (col0 + c) : (N - 1);
        const float* xp = X + cg;
#pragma unroll
        for (int h = 0; h < 2; ++h) {
            const int kb = kh + h * 16;
            float v[16];
#pragma unroll
            for (int j = 0; j < 16; ++j) v[j] = xp[(size_t)(kb + j) * N];
            uint32_t hb[8], lb[8];
#pragma unroll
            for (int j = 0; j < 8; ++j) {
                float v0 = v[2 * j], v1 = v[2 * j + 1];
                hb[j] = pack_bf16x2(v0, v1);
                lb[j] = pack_bf16x2(v0 - bf16_hi_val(v0), v1 - bf16_hi_val(v1));
            }
            const int base = c * PITCH + (kb >> 1);   // 16B-aligned (36%4==0, kb/2 multiple of 8)
            reinterpret_cast<uint4*>(&Xhi[base])[0]     = make_uint4(hb[0], hb[1], hb[2], hb[3]);
            reinterpret_cast<uint4*>(&Xhi[base + 4])[0] = make_uint4(hb[4], hb[5], hb[6], hb[7]);
            reinterpret_cast<uint4*>(&Xlo[base])[0]     = make_uint4(lb[0], lb[1], lb[2], lb[3]);
            reinterpret_cast<uint4*>(&Xlo[base + 4])[0] = make_uint4(lb[4], lb[5], lb[6], lb[7]);
        }
    }
    __syncthreads();

    float acc[4][2][4];
#pragma unroll
    for (int i = 0; i < 4; ++i)
#pragma unroll
        for (int jj = 0; jj < 2; ++jj)
#pragma unroll
            for (int r = 0; r < 4; ++r) acc[i][jj][r] = 0.0f;

    const int nrow0 = wid * 16 + g;

    // --- Fused 3-pass main loop: B-frags once per s, A-frags once per (s,i) ---
#pragma unroll
    for (int s = 0; s < 4; ++s) {
        const int bi0 = (nrow0)     * PITCH + s * 8 + t;
        const int bi1 = (nrow0 + 8) * PITCH + s * 8 + t;
        uint32_t bh00 = Xhi[bi0];
        uint32_t bh01 = Xhi[bi0 + 4];
        uint32_t bh10 = Xhi[bi1];
        uint32_t bh11 = Xhi[bi1 + 4];
        uint32_t bl00 = Xlo[bi0];
        uint32_t bl01 = Xlo[bi0 + 4];
        uint32_t bl10 = Xlo[bi1];
        uint32_t bl11 = Xlo[bi1 + 4];

#pragma unroll
        for (int i = 0; i < 4; ++i) {
            uint4 fH = fragH[(i * 4 + s) * 32 + lane];
            uint4 fL = fragL[(i * 4 + s) * 32 + lane];
            mma_bf16(acc[i][0][0], acc[i][0][1], acc[i][0][2], acc[i][0][3],
                     fH.x, fH.y, fH.z, fH.w, bh00, bh01);
            mma_bf16(acc[i][1][0], acc[i][1][1], acc[i][1][2], acc[i][1][3],
                     fH.x, fH.y, fH.z, fH.w, bh10, bh11);
            mma_bf16(acc[i][0][0], acc[i][0][1], acc[i][0][2], acc[i][0][3],
                     fH.x, fH.y, fH.z, fH.w, bl00, bl01);
            mma_bf16(acc[i][1][0], acc[i][1][1], acc[i][1][2], acc[i][1][3],
                     fH.x, fH.y, fH.z, fH.w, bl10, bl11);
            mma_bf16(acc[i][0][0], acc[i][0][1], acc[i][0][2], acc[i][0][3],
                     fL.x, fL.y, fL.z, fL.w, bh00, bh01);
            mma_bf16(acc[i][1][0], acc[i][1][1], acc[i][1][2], acc[i][1][3],
                     fL.x, fL.y, fL.z, fL.w, bh10, bh11);
        }
    }

    // --- Epilogue: adjacent-column float2 stores ---
#pragma unroll
    for (int i = 0; i < 4; ++i) {
#pragma unroll
        for (int jj = 0; jj < 2; ++jj) {
            const int colb = col0 + wid * 16 + jj * 8 + 2 * t;
            if (colb < N) {
                const int row = 16 * i + g;
                *reinterpret_cast<float2*>(out + (size_t)row * N + colb) =
                    make_float2(acc[i][jj][0], acc[i][jj][1]);
                *reinterpret_cast<float2*>(out + (size_t)(row + 8) * N + colb) =
                    make_float2(acc[i][jj][2], acc[i][jj][3]);
            }
        }
    }
}

// ---------------------------------------------------------------------------
// Inputs (metadata order): X [64*500000] f32, angles [2016] f32, mus [64] f32.
// Output: [64*500000] f32.
// ---------------------------------------------------------------------------
extern "C" void kernel_launch(void* const* d_in, const int* in_sizes, int n_in,
                              void* d_out, int out_size) {
    const float* X      = (const float*)d_in[0];
    const float* angles = (const float*)d_in[1];
    const float* mus    = (const float*)d_in[2];
    float* out = (float*)d_out;

    const int N = in_sizes[0] / NP;  // 500000

    cudaFuncSetAttribute(build_R_kernel,
                         cudaFuncAttributeMaxDynamicSharedMemorySize, BR_SMEM);
    build_R_kernel<<<1, 256, BR_SMEM>>>(angles, mus);

    cudaFuncSetAttribute(apply_mma_kernel,
                         cudaFuncAttributeMaxDynamicSharedMemorySize, APPLY_SMEM);
    const int grid = (N + 127) / 128;  // 3907
    apply_mma_kernel<<<grid, 256, APPLY_SMEM>>>(X, out, N);
}